// round 2
// baseline (speedup 1.0000x reference)
#include <cuda_runtime.h>

namespace {

constexpr int B = 8;
constexpr int N = 2048;
// log2(e) / TAU  with TAU = 1.0
constexpr float L2E = 1.4426950408889634f;

// Dual potentials, stored in base-2 domain (U = u*log2e, V = v*log2e).
__device__ float g_u[B * N];
__device__ float g_v[B * N];

__device__ __forceinline__ float ex2(float x) {
    float y; asm("ex2.approx.ftz.f32 %0, %1;" : "=f"(y) : "f"(x)); return y;
}
__device__ __forceinline__ float lg2(float x) {
    float y; asm("lg2.approx.f32 %0, %1;" : "=f"(y) : "f"(x)); return y;
}

// Row pass: U_i = log2( sum_j exp2(A_ij*L2E - V_j) ).
// One warp handles two rows of the SAME batch (rr and rr+1024) so the V
// vector load is shared. 1024 CTAs x 8 warps x 2 rows = 16384 rows.
template <bool FIRST>
__global__ __launch_bounds__(256) void row_pass(const float* __restrict__ A) {
    const int w    = blockIdx.x * 8 + (threadIdx.x >> 5);  // 0..8191
    const int lane = threadIdx.x & 31;
    const int b    = w >> 10;          // batch
    const int rr   = w & 1023;
    const int row0 = b * N + rr;
    const int row1 = row0 + 1024;

    const float4* a0 = reinterpret_cast<const float4*>(A) + (size_t)row0 * (N / 4);
    const float4* a1 = reinterpret_cast<const float4*>(A) + (size_t)row1 * (N / 4);
    const float4* v4 = reinterpret_cast<const float4*>(g_v) + (size_t)b * (N / 4);

    float s0 = 0.f, s1 = 0.f;
#pragma unroll 4
    for (int k = 0; k < 16; ++k) {
        const int idx = lane + 32 * k;
        float4 x0 = a0[idx];
        float4 x1 = a1[idx];
        float4 v;
        if (FIRST) { v.x = v.y = v.z = v.w = 0.f; }
        else       { v = v4[idx]; }
        s0 += ex2(fmaf(x0.x, L2E, -v.x));
        s0 += ex2(fmaf(x0.y, L2E, -v.y));
        s0 += ex2(fmaf(x0.z, L2E, -v.z));
        s0 += ex2(fmaf(x0.w, L2E, -v.w));
        s1 += ex2(fmaf(x1.x, L2E, -v.x));
        s1 += ex2(fmaf(x1.y, L2E, -v.y));
        s1 += ex2(fmaf(x1.z, L2E, -v.z));
        s1 += ex2(fmaf(x1.w, L2E, -v.w));
    }
#pragma unroll
    for (int o = 16; o; o >>= 1) {
        s0 += __shfl_xor_sync(0xffffffffu, s0, o);
        s1 += __shfl_xor_sync(0xffffffffu, s1, o);
    }
    if (lane == 0) {
        g_u[row0] = lg2(s0);
        g_u[row1] = lg2(s1);
    }
}

// Col pass: V_j = log2( sum_i exp2(A_ij*L2E - U_i) ).
// Grid: 8 batches x 64 column-stripes of 32. Block 256 = 32 cols x 8 row-groups.
// Each warp reads 32 consecutive floats per row (one aligned 128B line).
__global__ __launch_bounds__(256) void col_pass(const float* __restrict__ A) {
    const int b    = blockIdx.x >> 6;
    const int c0   = (blockIdx.x & 63) * 32;
    const int lane = threadIdx.x & 31;
    const int w    = threadIdx.x >> 5;

    const float* a = A + (size_t)b * N * N + c0 + lane;
    const float* u = g_u + b * N;

    float s = 0.f;
    for (int r = w; r < N; r += 32) {   // 4 rows per trip -> MLP 8
        float nu0 = -u[r];
        float nu1 = -u[r + 8];
        float nu2 = -u[r + 16];
        float nu3 = -u[r + 24];
        float x0 = a[(size_t)r * N];
        float x1 = a[(size_t)(r + 8)  * N];
        float x2 = a[(size_t)(r + 16) * N];
        float x3 = a[(size_t)(r + 24) * N];
        s += ex2(fmaf(x0, L2E, nu0));
        s += ex2(fmaf(x1, L2E, nu1));
        s += ex2(fmaf(x2, L2E, nu2));
        s += ex2(fmaf(x3, L2E, nu3));
    }

    __shared__ float red[256];
    red[threadIdx.x] = s;
    __syncthreads();
    if (w == 0) {
        float t = red[lane];
#pragma unroll
        for (int i = 1; i < 8; ++i) t += red[i * 32 + lane];
        g_v[b * N + c0 + lane] = lg2(t);
    }
}

// Final: P_ij = exp2( A_ij*L2E - U_i - V_j ).
__global__ __launch_bounds__(256) void final_pass(const float* __restrict__ A,
                                                  float* __restrict__ P) {
    const size_t i4 = (size_t)blockIdx.x * 256 + threadIdx.x;  // float4 index
    const int j4  = (int)(i4 & 511);       // N/4 = 512
    const int row = (int)(i4 >> 9);
    const int b   = row >> 11;

    float4 x = reinterpret_cast<const float4*>(A)[i4];
    const float nu = -g_u[row];
    float4 v = reinterpret_cast<const float4*>(g_v)[(size_t)b * 512 + j4];

    float4 o;
    o.x = ex2(fmaf(x.x, L2E, nu - v.x));
    o.y = ex2(fmaf(x.y, L2E, nu - v.y));
    o.z = ex2(fmaf(x.z, L2E, nu - v.z));
    o.w = ex2(fmaf(x.w, L2E, nu - v.w));
    reinterpret_cast<float4*>(P)[i4] = o;
}

}  // namespace

extern "C" void kernel_launch(void* const* d_in, const int* in_sizes, int n_in,
                              void* d_out, int out_size) {
    (void)in_sizes; (void)n_in; (void)out_size;
    const float* A = (const float*)d_in[0];
    float* P = (float*)d_out;

    // Iteration 1: v = 0, so the first row pass skips V loads entirely
    // (also makes every run deterministic: no stale g_v is ever read).
    row_pass<true><<<1024, 256>>>(A);
    col_pass<<<B * (N / 32), 256>>>(A);
    for (int it = 1; it < 20; ++it) {
        row_pass<false><<<1024, 256>>>(A);
        col_pass<<<B * (N / 32), 256>>>(A);
    }
    final_pass<<<(B * N * (N / 4)) / 256, 256>>>(A, P);
}

// round 3
// speedup vs baseline: 1.6623x; 1.6623x over previous
#include <cuda_runtime.h>
#include <cuda_fp16.h>

namespace {

constexpr int B = 8;
constexpr int N = 2048;
constexpr float L2E = 1.4426950408889634f;  // log2(e) / TAU, TAU = 1

// Dual potentials in base-2 domain (U = u*log2e, V = v*log2e).
__device__ __align__(16) float g_u[B * N];
__device__ __align__(16) float g_v[B * N];
// fp16 working copy of A * L2E (64 MB), as uint4 for 16B-aligned access.
__device__ uint4 g_h4[(size_t)B * N * N / 8];

__device__ __forceinline__ float ex2(float x) {
    float y; asm("ex2.approx.ftz.f32 %0, %1;" : "=f"(y) : "f"(x)); return y;
}
__device__ __forceinline__ float lg2(float x) {
    float y; asm("lg2.approx.f32 %0, %1;" : "=f"(y) : "f"(x)); return y;
}
__device__ __forceinline__ __half2 u2h(unsigned u) {
    __half2 h; *reinterpret_cast<unsigned*>(&h) = u; return h;
}
__device__ __forceinline__ unsigned h2u(__half2 h) {
    return *reinterpret_cast<unsigned*>(&h);
}

// ---------------------------------------------------------------------------
// Pass 1 fused: compute exact U_i = log2(sum_j exp2(A_ij*L2E))  (v == 0)
// AND write the fp16 working copy h = fp16(A*L2E).
// One warp = two rows of the same batch (rr, rr+1024). 1024 CTAs x 8 warps.
__global__ __launch_bounds__(256) void convert_row(const float* __restrict__ A) {
    const int w    = blockIdx.x * 8 + (threadIdx.x >> 5);
    const int lane = threadIdx.x & 31;
    const int b    = w >> 10;
    const int rr   = w & 1023;
    const int row0 = b * N + rr;
    const int row1 = row0 + 1024;

    const float4* a0 = reinterpret_cast<const float4*>(A) + (size_t)row0 * (N / 4);
    const float4* a1 = reinterpret_cast<const float4*>(A) + (size_t)row1 * (N / 4);
    uint4* h0 = g_h4 + (size_t)row0 * (N / 8);
    uint4* h1 = g_h4 + (size_t)row1 * (N / 8);

    float s0 = 0.f, s1 = 0.f;
#pragma unroll
    for (int k = 0; k < 8; ++k) {
        const int idx = lane + 32 * k;   // uint4 index (8 halfs) within the row
        float4 xa = a0[2 * idx], xb = a0[2 * idx + 1];
        float4 ya = a1[2 * idx], yb = a1[2 * idx + 1];

        uint4 o0, o1;
        o0.x = h2u(__floats2half2_rn(xa.x * L2E, xa.y * L2E));
        o0.y = h2u(__floats2half2_rn(xa.z * L2E, xa.w * L2E));
        o0.z = h2u(__floats2half2_rn(xb.x * L2E, xb.y * L2E));
        o0.w = h2u(__floats2half2_rn(xb.z * L2E, xb.w * L2E));
        o1.x = h2u(__floats2half2_rn(ya.x * L2E, ya.y * L2E));
        o1.y = h2u(__floats2half2_rn(ya.z * L2E, ya.w * L2E));
        o1.z = h2u(__floats2half2_rn(yb.x * L2E, yb.y * L2E));
        o1.w = h2u(__floats2half2_rn(yb.z * L2E, yb.w * L2E));
        h0[idx] = o0;
        h1[idx] = o1;

        s0 += ex2(xa.x * L2E) + ex2(xa.y * L2E) + ex2(xa.z * L2E) + ex2(xa.w * L2E);
        s0 += ex2(xb.x * L2E) + ex2(xb.y * L2E) + ex2(xb.z * L2E) + ex2(xb.w * L2E);
        s1 += ex2(ya.x * L2E) + ex2(ya.y * L2E) + ex2(ya.z * L2E) + ex2(ya.w * L2E);
        s1 += ex2(yb.x * L2E) + ex2(yb.y * L2E) + ex2(yb.z * L2E) + ex2(yb.w * L2E);
    }
#pragma unroll
    for (int o = 16; o; o >>= 1) {
        s0 += __shfl_xor_sync(0xffffffffu, s0, o);
        s1 += __shfl_xor_sync(0xffffffffu, s1, o);
    }
    if (lane == 0) { g_u[row0] = lg2(s0); g_u[row1] = lg2(s1); }
}

// ---------------------------------------------------------------------------
// fp16 row pass: U_i = log2(sum_j exp2(h_ij - V_j)).
__global__ __launch_bounds__(256) void row_h() {
    const int w    = blockIdx.x * 8 + (threadIdx.x >> 5);
    const int lane = threadIdx.x & 31;
    const int b    = w >> 10;
    const int rr   = w & 1023;
    const int row0 = b * N + rr;
    const int row1 = row0 + 1024;

    const uint4* h0 = g_h4 + (size_t)row0 * (N / 8);
    const uint4* h1 = g_h4 + (size_t)row1 * (N / 8);
    const float4* v4 = reinterpret_cast<const float4*>(g_v) + (size_t)b * (N / 4);

    float s0 = 0.f, s1 = 0.f;
#pragma unroll
    for (int k = 0; k < 8; ++k) {
        const int idx = lane + 32 * k;
        uint4 x = h0[idx];
        uint4 y = h1[idx];
        float4 va = v4[2 * idx], vb = v4[2 * idx + 1];
        float2 f;
        f = __half22float2(u2h(x.x)); s0 += ex2(f.x - va.x) + ex2(f.y - va.y);
        f = __half22float2(u2h(x.y)); s0 += ex2(f.x - va.z) + ex2(f.y - va.w);
        f = __half22float2(u2h(x.z)); s0 += ex2(f.x - vb.x) + ex2(f.y - vb.y);
        f = __half22float2(u2h(x.w)); s0 += ex2(f.x - vb.z) + ex2(f.y - vb.w);
        f = __half22float2(u2h(y.x)); s1 += ex2(f.x - va.x) + ex2(f.y - va.y);
        f = __half22float2(u2h(y.y)); s1 += ex2(f.x - va.z) + ex2(f.y - va.w);
        f = __half22float2(u2h(y.z)); s1 += ex2(f.x - vb.x) + ex2(f.y - vb.y);
        f = __half22float2(u2h(y.w)); s1 += ex2(f.x - vb.z) + ex2(f.y - vb.w);
    }
#pragma unroll
    for (int o = 16; o; o >>= 1) {
        s0 += __shfl_xor_sync(0xffffffffu, s0, o);
        s1 += __shfl_xor_sync(0xffffffffu, s1, o);
    }
    if (lane == 0) { g_u[row0] = lg2(s0); g_u[row1] = lg2(s1); }
}

// ---------------------------------------------------------------------------
// fp16 col pass: V_j = log2(sum_i exp2(h_ij - U_i)).
// 64-col stripes (32 half2 / 128B per warp-row). Block 512 = 16 warps;
// warp handles 8 consecutive rows per trip (8 loads in flight). Grid 8*32.
__global__ __launch_bounds__(512) void col_h() {
    const int b    = blockIdx.x >> 5;
    const int c0h  = (blockIdx.x & 31) * 32;           // half2-column offset
    const int lane = threadIdx.x & 31;
    const int w    = threadIdx.x >> 5;

    const __half2* a = reinterpret_cast<const __half2*>(g_h4)
                     + (size_t)b * N * (N / 2) + c0h + lane;
    const float* u = g_u + b * N;

    float s0 = 0.f, s1 = 0.f;
    for (int t = 0; t < 16; ++t) {
        const int r = t * 128 + w * 8;
#pragma unroll
        for (int i = 0; i < 8; ++i) {
            float2 f = __half22float2(a[(size_t)(r + i) * (N / 2)]);
            float nu = -u[r + i];
            s0 += ex2(f.x + nu);
            s1 += ex2(f.y + nu);
        }
    }

    __shared__ float red[16][64];
    red[w][2 * lane]     = s0;
    red[w][2 * lane + 1] = s1;
    __syncthreads();
    if (threadIdx.x < 64) {
        float t = 0.f;
#pragma unroll
        for (int i = 0; i < 16; ++i) t += red[i][threadIdx.x];
        g_v[b * N + c0h * 2 + threadIdx.x] = lg2(t);
    }
}

// ---------------------------------------------------------------------------
// fp32 exact row pass (final iterations): U_i = log2(sum_j exp2(A_ij*L2E - V_j)).
__global__ __launch_bounds__(256) void row_f(const float* __restrict__ A) {
    const int w    = blockIdx.x * 8 + (threadIdx.x >> 5);
    const int lane = threadIdx.x & 31;
    const int b    = w >> 10;
    const int rr   = w & 1023;
    const int row0 = b * N + rr;
    const int row1 = row0 + 1024;

    const float4* a0 = reinterpret_cast<const float4*>(A) + (size_t)row0 * (N / 4);
    const float4* a1 = reinterpret_cast<const float4*>(A) + (size_t)row1 * (N / 4);
    const float4* v4 = reinterpret_cast<const float4*>(g_v) + (size_t)b * (N / 4);

    float s0 = 0.f, s1 = 0.f;
#pragma unroll
    for (int k = 0; k < 8; ++k) {
        const int idx = lane + 32 * k;
        float4 xa = a0[2 * idx], xb = a0[2 * idx + 1];
        float4 ya = a1[2 * idx], yb = a1[2 * idx + 1];
        float4 va = v4[2 * idx], vb = v4[2 * idx + 1];
        s0 += ex2(fmaf(xa.x, L2E, -va.x)) + ex2(fmaf(xa.y, L2E, -va.y));
        s0 += ex2(fmaf(xa.z, L2E, -va.z)) + ex2(fmaf(xa.w, L2E, -va.w));
        s0 += ex2(fmaf(xb.x, L2E, -vb.x)) + ex2(fmaf(xb.y, L2E, -vb.y));
        s0 += ex2(fmaf(xb.z, L2E, -vb.z)) + ex2(fmaf(xb.w, L2E, -vb.w));
        s1 += ex2(fmaf(ya.x, L2E, -va.x)) + ex2(fmaf(ya.y, L2E, -va.y));
        s1 += ex2(fmaf(ya.z, L2E, -va.z)) + ex2(fmaf(ya.w, L2E, -va.w));
        s1 += ex2(fmaf(yb.x, L2E, -vb.x)) + ex2(fmaf(yb.y, L2E, -vb.y));
        s1 += ex2(fmaf(yb.z, L2E, -vb.z)) + ex2(fmaf(yb.w, L2E, -vb.w));
    }
#pragma unroll
    for (int o = 16; o; o >>= 1) {
        s0 += __shfl_xor_sync(0xffffffffu, s0, o);
        s1 += __shfl_xor_sync(0xffffffffu, s1, o);
    }
    if (lane == 0) { g_u[row0] = lg2(s0); g_u[row1] = lg2(s1); }
}

// ---------------------------------------------------------------------------
// fp32 exact col pass: V_j = log2(sum_i exp2(A_ij*L2E - U_i)).
// 32-col stripes, block 256 = 8 warps, 8 rows in flight per warp. Grid 8*64.
__global__ __launch_bounds__(256) void col_f(const float* __restrict__ A) {
    const int b    = blockIdx.x >> 6;
    const int c0   = (blockIdx.x & 63) * 32;
    const int lane = threadIdx.x & 31;
    const int w    = threadIdx.x >> 5;

    const float* a = A + (size_t)b * N * N + c0 + lane;
    const float* u = g_u + b * N;

    float s = 0.f;
    for (int t = 0; t < 32; ++t) {
        const int r = t * 64 + w * 8;
#pragma unroll
        for (int i = 0; i < 8; ++i) {
            s += ex2(fmaf(a[(size_t)(r + i) * N], L2E, -u[r + i]));
        }
    }

    __shared__ float red[8][32];
    red[w][lane] = s;
    __syncthreads();
    if (threadIdx.x < 32) {
        float t = 0.f;
#pragma unroll
        for (int i = 0; i < 8; ++i) t += red[i][threadIdx.x];
        g_v[b * N + c0 + threadIdx.x] = lg2(t);
    }
}

// ---------------------------------------------------------------------------
// Final: P_ij = exp2(A_ij*L2E - U_i - V_j).  Two float4 per thread.
__global__ __launch_bounds__(256) void final_pass(const float* __restrict__ A,
                                                  float* __restrict__ P) {
    const size_t i4 = ((size_t)blockIdx.x * 256 + threadIdx.x) * 2;
    const int j4  = (int)(i4 & 511);       // N/4 = 512
    const int row = (int)(i4 >> 9);
    const int b   = row >> 11;

    const float4* A4 = reinterpret_cast<const float4*>(A);
    const float4* V4 = reinterpret_cast<const float4*>(g_v) + (size_t)b * 512;
    float4 x0 = A4[i4], x1 = A4[i4 + 1];
    float4 v0 = V4[j4], v1 = V4[j4 + 1];
    const float nu = -g_u[row];

    float4 o0, o1;
    o0.x = ex2(fmaf(x0.x, L2E, nu - v0.x));
    o0.y = ex2(fmaf(x0.y, L2E, nu - v0.y));
    o0.z = ex2(fmaf(x0.z, L2E, nu - v0.z));
    o0.w = ex2(fmaf(x0.w, L2E, nu - v0.w));
    o1.x = ex2(fmaf(x1.x, L2E, nu - v1.x));
    o1.y = ex2(fmaf(x1.y, L2E, nu - v1.y));
    o1.z = ex2(fmaf(x1.z, L2E, nu - v1.z));
    o1.w = ex2(fmaf(x1.w, L2E, nu - v1.w));
    float4* P4 = reinterpret_cast<float4*>(P);
    P4[i4]     = o0;
    P4[i4 + 1] = o1;
}

}  // namespace

extern "C" void kernel_launch(void* const* d_in, const int* in_sizes, int n_in,
                              void* d_out, int out_size) {
    (void)in_sizes; (void)n_in; (void)out_size;
    const float* A = (const float*)d_in[0];
    float* P = (float*)d_out;

    // Pair 1: exact row pass fused with fp16 conversion, then fp16 col pass.
    convert_row<<<1024, 256>>>(A);
    col_h<<<8 * 32, 512>>>();
    // Pairs 2..16: fp16 working copy (L2-resident).
    for (int it = 0; it < 15; ++it) {
        row_h<<<1024, 256>>>();
        col_h<<<8 * 32, 512>>>();
    }
    // Pairs 17..20: exact fp32 to contract fp16 quantization error away.
    for (int it = 0; it < 4; ++it) {
        row_f<<<1024, 256>>>(A);
        col_f<<<8 * 64, 256>>>(A);
    }
    final_pass<<<(B * N * (N / 4)) / 512, 256>>>(A, P);
}